// round 2
// baseline (speedup 1.0000x reference)
#include <cuda_runtime.h>
#include <float.h>

// Problem constants
#define Bn    8
#define Nn    256
#define Dd    128
#define MIDn  128
#define FEATn 256   // 2*D

// Scratch (device globals: no runtime allocation allowed)
__device__ float g_msg1[Bn * Nn * MIDn];   // (B,N,MID)
__device__ float g_msg2[Bn * Nn * MIDn];   // (B,N,MID)
__device__ float g_msgg[Bn * MIDn];        // (B,MID)
__device__ float g_base[Bn * Nn * MIDn];   // features@Wo1 + bo1 + bo2

// ---- packed f32x2 helpers (sm_103a) ------------------------------------
__device__ __forceinline__ unsigned long long pack2(float lo, float hi) {
    unsigned long long u;
    asm("mov.b64 %0, {%1, %2};" : "=l"(u) : "f"(lo), "f"(hi));
    return u;
}
__device__ __forceinline__ void unpack2(unsigned long long u, float& lo, float& hi) {
    asm("mov.b64 {%0, %1}, %2;" : "=f"(lo), "=f"(hi) : "l"(u));
}
__device__ __forceinline__ void ffma2(unsigned long long& d,
                                      unsigned long long a,
                                      unsigned long long b) {
    asm("fma.rn.f32x2 %0, %1, %2, %0;" : "+l"(d) : "l"(a), "l"(b));
}

// ========================================================================
// Kernel 1: msg_1, msg_2, base  (features = concat(n_features, hidden))
// 8 rows per block, 128 threads (thread = output channel m).
// ========================================================================
__global__ __launch_bounds__(128) void prep_kernel(
    const float* __restrict__ hidden, const float* __restrict__ nfeat,
    const float* __restrict__ W1, const float* __restrict__ b1,
    const float* __restrict__ W2, const float* __restrict__ b2,
    const float* __restrict__ Wo1, const float* __restrict__ bo1,
    const float* __restrict__ bo2)
{
    const int R = 8;
    __shared__ float fs[R * FEATn];
    const int m = threadIdx.x;
    const int row0 = blockIdx.x * R;   // flattened (b,n) row

    #pragma unroll
    for (int r = 0; r < R; r++) {
        const int row = row0 + r;
        fs[r * FEATn + m]      = nfeat[row * Dd + m];    // features[:,0:128]
        fs[r * FEATn + Dd + m] = hidden[row * Dd + m];   // features[:,128:256]
    }
    __syncthreads();

    float a1[R], a2[R], ao[R];
    const float bb1 = b1[m];
    const float bb2 = b2[m];
    const float bbo = bo1[m] + bo2[m];
    #pragma unroll
    for (int r = 0; r < R; r++) { a1[r] = bb1; a2[r] = bb2; ao[r] = bbo; }

    for (int f = 0; f < FEATn; f++) {
        const float w1 = __ldg(&W1[f * MIDn + m]);
        const float w2 = __ldg(&W2[f * MIDn + m]);
        const float wo = __ldg(&Wo1[f * MIDn + m]);
        #pragma unroll
        for (int r = 0; r < R; r++) {
            const float s = fs[r * FEATn + f];
            a1[r] = fmaf(s, w1, a1[r]);
            a2[r] = fmaf(s, w2, a2[r]);
            ao[r] = fmaf(s, wo, ao[r]);
        }
    }
    #pragma unroll
    for (int r = 0; r < R; r++) {
        g_msg1[(row0 + r) * MIDn + m] = a1[r];
        g_msg2[(row0 + r) * MIDn + m] = a2[r];
        g_base[(row0 + r) * MIDn + m] = ao[r];
    }
}

// ========================================================================
// Kernel 2: msg_g = g_features @ Wg + bg   (tiny)
// ========================================================================
__global__ __launch_bounds__(128) void msgg_kernel(
    const float* __restrict__ gfeat, const float* __restrict__ Wg,
    const float* __restrict__ bg)
{
    const int m = threadIdx.x;
    const int b = blockIdx.x;
    float acc = bg[m];
    for (int k = 0; k < Dd; k++)
        acc = fmaf(gfeat[b * Dd + k], __ldg(&Wg[k * MIDn + m]), acc);
    g_msgg[b * MIDn + m] = acc;
}

// ========================================================================
// Kernel 3 (fused main pass): one CTA per (b, j).
//   out[b,j,m] = base[b,j,m]
//              + sum_k Wo2[k,m] * max_i adj[b,i,j] *
//                    ( e[b,i,j,:]@We[:,m] + be[m]
//                      + msg1[b,j,m] + msg2[b,i,m] + msgg[b,m] )
// We column held in 64 packed f32x2 registers; e rows staged via smem in
// 8-row chunks; dot via two fma.rn.f32x2 chains.
// ========================================================================
__global__ __launch_bounds__(128, 2) void main_kernel(
    const float* __restrict__ efeat, const float* __restrict__ adj,
    const float* __restrict__ We,    const float* __restrict__ be,
    const float* __restrict__ Wo2,   float* __restrict__ out)
{
    __shared__ __align__(16) float esm[8 * Dd];     // 8 e-rows
    __shared__ float m2sm[8 * MIDn];                // matching msg2 rows
    __shared__ float adjsm[8];
    __shared__ float msgsm[MIDn];

    const int m  = threadIdx.x;
    const int bj = blockIdx.x;       // b*256 + j
    const int b  = bj >> 8;
    const int j  = bj & 255;

    // We[:,m] packed into 64 f32x2 registers (k-pairs)
    unsigned long long w2[64];
    #pragma unroll
    for (int kk = 0; kk < 64; kk++)
        w2[kk] = pack2(__ldg(&We[(2 * kk) * MIDn + m]),
                       __ldg(&We[(2 * kk + 1) * MIDn + m]));

    const float cst = g_msg1[bj * MIDn + m] + g_msgg[b * MIDn + m] + be[m];
    float best = -FLT_MAX;

    const float* ebase  = efeat + ((long)b * Nn * Nn + j) * Dd;  // + i*Nn*Dd
    const float* m2base = g_msg2 + b * Nn * MIDn;
    const float* adjbase = adj + (long)(b * Nn) * Nn + j;        // + i*Nn

    for (int c = 0; c < Nn / 8; c++) {
        // stage 8 rows of e and msg2 (coalesced), 8 adj scalars
        #pragma unroll
        for (int r = 0; r < 8; r++) {
            const int i = c * 8 + r;
            esm[r * Dd + m]    = ebase[(long)i * Nn * Dd + m];
            m2sm[r * MIDn + m] = m2base[i * MIDn + m];
        }
        if (m < 8) adjsm[m] = adjbase[(long)(c * 8 + m) * Nn];
        __syncthreads();

        #pragma unroll 1
        for (int r = 0; r < 8; r++) {
            const ulonglong2* er = (const ulonglong2*)(esm + r * Dd);
            unsigned long long acc0 = 0ull, acc1 = 0ull;   // {0.f,0.f}
            #pragma unroll
            for (int q = 0; q < 32; q++) {
                const ulonglong2 ev = er[q];               // e[4q..4q+3]
                ffma2(acc0, ev.x, w2[2 * q]);
                ffma2(acc1, ev.y, w2[2 * q + 1]);
            }
            float x0, x1, y0, y1;
            unpack2(acc0, x0, x1);
            unpack2(acc1, y0, y1);
            const float dot = (x0 + y0) + (x1 + y1);
            const float msg = dot + cst + m2sm[r * MIDn + m];
            best = fmaxf(best, adjsm[r] * msg);
        }
        __syncthreads();
    }

    // epilogue: out = base + msgs @ Wo2
    msgsm[m] = best;
    __syncthreads();
    float o = g_base[bj * MIDn + m];
    for (int k = 0; k < MIDn; k++)
        o = fmaf(msgsm[k], __ldg(&Wo2[k * MIDn + m]), o);
    out[bj * MIDn + m] = o;
}

// ========================================================================
extern "C" void kernel_launch(void* const* d_in, const int* in_sizes, int n_in,
                              void* d_out, int out_size)
{
    const float* hidden = (const float*)d_in[0];
    const float* nfeat  = (const float*)d_in[1];
    const float* efeat  = (const float*)d_in[2];
    const float* gfeat  = (const float*)d_in[3];
    const float* adj    = (const float*)d_in[4];
    const float* W1  = (const float*)d_in[5];
    const float* b1  = (const float*)d_in[6];
    const float* W2  = (const float*)d_in[7];
    const float* b2  = (const float*)d_in[8];
    const float* We  = (const float*)d_in[9];
    const float* be  = (const float*)d_in[10];
    const float* Wg  = (const float*)d_in[11];
    const float* bg  = (const float*)d_in[12];
    const float* Wo1 = (const float*)d_in[13];
    const float* bo1 = (const float*)d_in[14];
    const float* Wo2 = (const float*)d_in[15];
    const float* bo2 = (const float*)d_in[16];
    float* out = (float*)d_out;

    prep_kernel<<<(Bn * Nn) / 8, 128>>>(hidden, nfeat, W1, b1, W2, b2,
                                        Wo1, bo1, bo2);
    msgg_kernel<<<Bn, 128>>>(gfeat, Wg, bg);
    main_kernel<<<Bn * Nn, 128>>>(efeat, adj, We, be, Wo2, out);
}

// round 4
// speedup vs baseline: 3.3934x; 3.3934x over previous
#include <cuda_runtime.h>
#include <cstdint>
#include <float.h>

// Problem constants
#define Bn    8
#define Nn    256
#define Dd    128
#define MIDn  128
#define FEATn 256   // 2*D

// Scratch (device globals; no runtime allocation allowed)
__device__ float g_msg1[Bn * Nn * MIDn];
__device__ float g_msg2[Bn * Nn * MIDn];
__device__ float g_msgg[Bn * MIDn];
__device__ float g_base[Bn * Nn * MIDn];        // features@Wo1 + bo1 + bo2
__device__ unsigned g_WeTpack[MIDn * Dd];       // We^T in A-fragment order (tf32 bits)

// ---------------- PTX helpers (arch-agnostic, sm_80+) --------------------
__device__ __forceinline__ uint32_t smem_u32(const void* p) {
    uint32_t a;
    asm("{ .reg .u64 t; cvta.to.shared.u64 t, %1; cvt.u32.u64 %0, t; }"
        : "=r"(a) : "l"(p));
    return a;
}
__device__ __forceinline__ void cp16(uint32_t dst, const void* src) {
    asm volatile("cp.async.cg.shared.global [%0], [%1], 16;"
                 :: "r"(dst), "l"(src) : "memory");
}
__device__ __forceinline__ void cp_commit() {
    asm volatile("cp.async.commit_group;" ::: "memory");
}
template <int N> __device__ __forceinline__ void cp_wait() {
    asm volatile("cp.async.wait_group %0;" :: "n"(N) : "memory");
}
__device__ __forceinline__ unsigned tf32r(float x) {
    unsigned u;
    asm("cvt.rna.tf32.f32 %0, %1;" : "=r"(u) : "f"(x));
    return u;
}
// m16n8k8 tf32 HMMA: C += A*B ; A row-major (m x k), B col-major frag (k x n)
__device__ __forceinline__ void mma8(float* c, uint4 a, unsigned b0, unsigned b1) {
    asm volatile(
        "mma.sync.aligned.m16n8k8.row.col.f32.tf32.tf32.f32 "
        "{%0,%1,%2,%3},{%4,%5,%6,%7},{%8,%9},{%0,%1,%2,%3};"
        : "+f"(c[0]), "+f"(c[1]), "+f"(c[2]), "+f"(c[3])
        : "r"(a.x), "r"(a.y), "r"(a.z), "r"(a.w), "r"(b0), "r"(b1));
}

// Dynamic smem layout (bytes). E rows padded to 132 floats (conflict-free B loads).
#define EPADF    132
#define EROWB    (EPADF * 4)               // 528
#define ECHUNKB  (32 * EROWB)              // 16896
#define SM_WET   0                          // 65536: A fragments
#define SM_E0    65536
#define SM_E1    (SM_E0 + ECHUNKB)          // 82432
#define SM_ADJ   (SM_E1 + ECHUNKB)          // 99328 (256 floats)
#define SM_BEST  (SM_ADJ + 1024)            // 100352 (128 floats)
#define SM_TOTAL (SM_BEST + 512)            // 100864

// ========================================================================
// Kernel 0: pack We^T into A-fragment order, tf32-rounded.
// Fragment block (mtg, kt) = 32 lanes x 4 regs (512B). For lane l, reg e:
//   m = mtg*16 + (l>>2) + (e&1)*8 ;  k = kt*8 + (l&3) + (e>>1)*4
// ========================================================================
__global__ __launch_bounds__(256) void wet_kernel(const float* __restrict__ We) {
    const int idx = blockIdx.x * 256 + threadIdx.x;    // 0..16383
    const int blk = idx >> 7;          // 0..127
    const int mtg = blk >> 4, kt = blk & 15;
    const int l = (idx >> 2) & 31, e = idx & 3;
    const int m = mtg * 16 + (l >> 2) + (e & 1) * 8;
    const int k = kt * 8 + (l & 3) + ((e >> 1)) * 4;
    g_WeTpack[idx] = tf32r(We[k * MIDn + m]);
}

// ========================================================================
// Kernel 1: msg1, msg2, base. 256 threads: m = tid&127, f-half = tid>>7.
// ========================================================================
__global__ __launch_bounds__(256) void prep_kernel(
    const float* __restrict__ hidden, const float* __restrict__ nfeat,
    const float* __restrict__ W1, const float* __restrict__ b1,
    const float* __restrict__ W2, const float* __restrict__ b2,
    const float* __restrict__ Wo1, const float* __restrict__ bo1,
    const float* __restrict__ bo2)
{
    __shared__ float fs[8 * FEATn];
    __shared__ float red[3 * 8 * MIDn];
    const int tid = threadIdx.x;
    const int m = tid & 127, h = tid >> 7;
    const int row0 = blockIdx.x * 8;

    for (int idx = tid; idx < 8 * FEATn; idx += 256) {
        int r = idx >> 8, c = idx & 255;
        fs[idx] = (c < Dd) ? nfeat[(row0 + r) * Dd + c]
                           : hidden[(row0 + r) * Dd + (c - Dd)];
    }
    __syncthreads();

    float a1[8], a2[8], ao[8];
    #pragma unroll
    for (int r = 0; r < 8; r++) { a1[r] = 0.f; a2[r] = 0.f; ao[r] = 0.f; }

    const int fbase = h * 128;
    #pragma unroll 4
    for (int ff = 0; ff < 128; ff++) {
        const int f = fbase + ff;
        const float w1 = __ldg(&W1[f * MIDn + m]);
        const float w2 = __ldg(&W2[f * MIDn + m]);
        const float wo = __ldg(&Wo1[f * MIDn + m]);
        #pragma unroll
        for (int r = 0; r < 8; r++) {
            const float s = fs[r * FEATn + f];
            a1[r] = fmaf(s, w1, a1[r]);
            a2[r] = fmaf(s, w2, a2[r]);
            ao[r] = fmaf(s, wo, ao[r]);
        }
    }
    if (h == 1) {
        #pragma unroll
        for (int r = 0; r < 8; r++) {
            red[0 * 1024 + r * 128 + m] = a1[r];
            red[1 * 1024 + r * 128 + m] = a2[r];
            red[2 * 1024 + r * 128 + m] = ao[r];
        }
    }
    __syncthreads();
    if (h == 0) {
        const float bb1 = b1[m], bb2 = b2[m], bbo = bo1[m] + bo2[m];
        #pragma unroll
        for (int r = 0; r < 8; r++) {
            const int row = row0 + r;
            g_msg1[row * MIDn + m] = a1[r] + red[0 * 1024 + r * 128 + m] + bb1;
            g_msg2[row * MIDn + m] = a2[r] + red[1 * 1024 + r * 128 + m] + bb2;
            g_base[row * MIDn + m] = ao[r] + red[2 * 1024 + r * 128 + m] + bbo;
        }
    }
}

// ========================================================================
// Kernel 2: msg_g (tiny)
// ========================================================================
__global__ __launch_bounds__(128) void msgg_kernel(
    const float* __restrict__ gfeat, const float* __restrict__ Wg,
    const float* __restrict__ bg)
{
    const int m = threadIdx.x, b = blockIdx.x;
    float acc = bg[m];
    for (int k = 0; k < Dd; k++)
        acc = fmaf(gfeat[b * Dd + k], __ldg(&Wg[k * MIDn + m]), acc);
    g_msgg[b * MIDn + m] = acc;
}

// ========================================================================
// Kernel 3: fused main pass, mma.sync tf32.
// CTA per (b,j): D[m][i] = sum_k We[k][m]*e[b,i,j,k]; masked max over i in
// registers; epilogue out = base + best@Wo2.
// ========================================================================
__device__ __forceinline__ void stage_chunk(uint32_t ebuf, const float* ebj,
                                            int c, int tid)
{
    const int col = tid & 31;       // 16B chunk within a 128-float row
    const int r0  = tid >> 5;       // 0..3
    #pragma unroll
    for (int rr = 0; rr < 8; rr++) {
        const int r = r0 + rr * 4;                  // row within chunk (0..31)
        const long i = c * 32 + r;
        cp16(ebuf + r * EROWB + col * 16, ebj + i * (Nn * Dd) + col * 4);
    }
}

__global__ __launch_bounds__(128, 2) void main_kernel(
    const float* __restrict__ efeat, const float* __restrict__ adj,
    const float* __restrict__ be,    const float* __restrict__ Wo2,
    float* __restrict__ out)
{
    extern __shared__ __align__(16) char smem[];
    const uint32_t sb = smem_u32(smem);
    const int tid = threadIdx.x;
    const int w = tid >> 5, l = tid & 31, g = l >> 2, t = l & 3;
    const int bj = blockIdx.x, b = bj >> 8, j = bj & 255;

    const float* ebj = efeat + (long)b * (Nn * Nn * Dd) + (long)j * Dd;

    // Stage A fragments (64KB flat copy) + chunk 0 -> group 0; chunk 1 -> group 1
    for (int q = tid; q < 4096; q += 128)
        cp16(sb + SM_WET + q * 16, g_WeTpack + q * 4);
    stage_chunk(sb + SM_E0, ebj, 0, tid);
    cp_commit();
    stage_chunk(sb + SM_E1, ebj, 1, tid);
    cp_commit();

    // adj column
    float* adjs = (float*)(smem + SM_ADJ);
    for (int i = tid; i < Nn; i += 128)
        adjs[i] = adj[((long)b * Nn + i) * Nn + j];

    // per-thread constants: 4 m values (slot s: m = w*32 + (s>>1)*16 + g + (s&1)*8)
    float cst[4], best[4];
    #pragma unroll
    for (int s = 0; s < 4; s++) {
        const int m = w * 32 + (s >> 1) * 16 + g + (s & 1) * 8;
        cst[s] = g_msg1[bj * MIDn + m] + g_msgg[b * MIDn + m] + be[m];
        best[s] = -FLT_MAX;
    }

    const float* m2 = g_msg2 + ((long)b << 15);   // msg2[b]
    const uint32_t wetbase = sb + SM_WET + ((w * 2) * 16) * 512 + l * 16;

    #pragma unroll 1
    for (int c = 0; c < 8; c++) {
        if (c < 7) { cp_wait<1>(); } else { cp_wait<0>(); }
        __syncthreads();
        const char* eb = smem + ((c & 1) ? SM_E1 : SM_E0);

        float acc[2][4][4];
        #pragma unroll
        for (int mt = 0; mt < 2; mt++)
            #pragma unroll
            for (int nt = 0; nt < 4; nt++)
                #pragma unroll
                for (int r = 0; r < 4; r++) acc[mt][nt][r] = 0.f;

        #pragma unroll
        for (int kt = 0; kt < 16; kt++) {
            const uint4 A0 = *(const uint4*)(smem + SM_WET
                              + (((w * 2 + 0) * 16 + kt) << 9) + (l << 4));
            const uint4 A1 = *(const uint4*)(smem + SM_WET
                              + (((w * 2 + 1) * 16 + kt) << 9) + (l << 4));
            #pragma unroll
            for (int nt = 0; nt < 4; nt++) {
                const float* ep = (const float*)eb + (nt * 8 + g) * EPADF
                                  + kt * 8 + t;
                const unsigned b0 = tf32r(ep[0]);
                const unsigned b1 = tf32r(ep[4]);
                mma8(acc[0][nt], A0, b0, b1);
                mma8(acc[1][nt], A1, b0, b1);
            }
        }

        // fold this chunk into running max
        #pragma unroll
        for (int mt = 0; mt < 2; mt++)
            #pragma unroll
            for (int nt = 0; nt < 4; nt++) {
                const int i0 = c * 32 + nt * 8 + 2 * t;
                const float aj0 = adjs[i0], aj1 = adjs[i0 + 1];
                #pragma unroll
                for (int h = 0; h < 2; h++) {
                    const int m = w * 32 + mt * 16 + g + h * 8;
                    const int s = mt * 2 + h;
                    const float v0 = (acc[mt][nt][2 * h] + cst[s]
                                      + __ldg(m2 + (long)i0 * MIDn + m)) * aj0;
                    const float v1 = (acc[mt][nt][2 * h + 1] + cst[s]
                                      + __ldg(m2 + (long)(i0 + 1) * MIDn + m)) * aj1;
                    best[s] = fmaxf(best[s], fmaxf(v0, v1));
                }
            }
        __syncthreads();
        if (c < 6) { stage_chunk(sb + ((c & 1) ? SM_E1 : SM_E0), ebj, c + 2, tid);
                     cp_commit(); }
    }

    // reduce max across the 4 lanes of each quad (t = 0..3)
    #pragma unroll
    for (int s = 0; s < 4; s++) {
        best[s] = fmaxf(best[s], __shfl_xor_sync(0xFFFFFFFFu, best[s], 1));
        best[s] = fmaxf(best[s], __shfl_xor_sync(0xFFFFFFFFu, best[s], 2));
    }
    float* bestsm = (float*)(smem + SM_BEST);
    if (t == 0) {
        #pragma unroll
        for (int s = 0; s < 4; s++)
            bestsm[w * 32 + (s >> 1) * 16 + g + (s & 1) * 8] = best[s];
    }
    __syncthreads();

    // out = base + best @ Wo2
    float o = g_base[bj * MIDn + tid];
    #pragma unroll 8
    for (int k = 0; k < MIDn; k++)
        o = fmaf(bestsm[k], __ldg(&Wo2[(k << 7) + tid]), o);
    out[bj * MIDn + tid] = o;
}

// ========================================================================
extern "C" void kernel_launch(void* const* d_in, const int* in_sizes, int n_in,
                              void* d_out, int out_size)
{
    const float* hidden = (const float*)d_in[0];
    const float* nfeat  = (const float*)d_in[1];
    const float* efeat  = (const float*)d_in[2];
    const float* gfeat  = (const float*)d_in[3];
    const float* adj    = (const float*)d_in[4];
    const float* W1  = (const float*)d_in[5];
    const float* b1  = (const float*)d_in[6];
    const float* W2  = (const float*)d_in[7];
    const float* b2  = (const float*)d_in[8];
    const float* We  = (const float*)d_in[9];
    const float* be  = (const float*)d_in[10];
    const float* Wg  = (const float*)d_in[11];
    const float* bg  = (const float*)d_in[12];
    const float* Wo1 = (const float*)d_in[13];
    const float* bo1 = (const float*)d_in[14];
    const float* Wo2 = (const float*)d_in[15];
    const float* bo2 = (const float*)d_in[16];
    float* out = (float*)d_out;

    static int smem_set = 0;
    if (!smem_set) {
        cudaFuncSetAttribute(main_kernel,
                             cudaFuncAttributeMaxDynamicSharedMemorySize,
                             SM_TOTAL);
        smem_set = 1;
    }

    wet_kernel<<<64, 256>>>(We);
    prep_kernel<<<(Bn * Nn) / 8, 256>>>(hidden, nfeat, W1, b1, W2, b2,
                                        Wo1, bo1, bo2);
    msgg_kernel<<<Bn, 128>>>(gfeat, Wg, bg);
    main_kernel<<<Bn * Nn, 128, SM_TOTAL>>>(efeat, adj, be, Wo2, out);
}

// round 5
// speedup vs baseline: 3.7118x; 1.0938x over previous
#include <cuda_runtime.h>
#include <cstdint>
#include <float.h>

// Problem constants
#define Bn    8
#define Nn    256
#define Dd    128
#define MIDn  128
#define FEATn 256   // 2*D

// Scratch (device globals; no runtime allocation allowed)
__device__ float g_msg1[Bn * Nn * MIDn];
__device__ float g_msg2[Bn * Nn * MIDn];
__device__ float g_msgg[Bn * MIDn];
__device__ float g_base[Bn * Nn * MIDn];        // features@Wo1 + bo1 + bo2
__device__ unsigned g_WeTpack[MIDn * Dd];       // We^T in A-fragment order (tf32 bits)

// ---------------- PTX helpers (arch-agnostic, sm_80+) --------------------
__device__ __forceinline__ uint32_t smem_u32(const void* p) {
    uint32_t a;
    asm("{ .reg .u64 t; cvta.to.shared.u64 t, %1; cvt.u32.u64 %0, t; }"
        : "=r"(a) : "l"(p));
    return a;
}
__device__ __forceinline__ void cp16(uint32_t dst, const void* src) {
    asm volatile("cp.async.cg.shared.global [%0], [%1], 16;"
                 :: "r"(dst), "l"(src) : "memory");
}
__device__ __forceinline__ void cp4(uint32_t dst, const void* src) {
    asm volatile("cp.async.ca.shared.global [%0], [%1], 4;"
                 :: "r"(dst), "l"(src) : "memory");
}
__device__ __forceinline__ void cp_commit() {
    asm volatile("cp.async.commit_group;" ::: "memory");
}
template <int N> __device__ __forceinline__ void cp_wait() {
    asm volatile("cp.async.wait_group %0;" :: "n"(N) : "memory");
}
__device__ __forceinline__ unsigned tf32r(float x) {
    unsigned u;
    asm("cvt.rna.tf32.f32 %0, %1;" : "=r"(u) : "f"(x));
    return u;
}
// m16n8k8 tf32 HMMA: C += A*B ; A row-major (m x k), B col-major frag (k x n)
__device__ __forceinline__ void mma8(float* c, uint4 a, unsigned b0, unsigned b1) {
    asm volatile(
        "mma.sync.aligned.m16n8k8.row.col.f32.tf32.tf32.f32 "
        "{%0,%1,%2,%3},{%4,%5,%6,%7},{%8,%9},{%0,%1,%2,%3};"
        : "+f"(c[0]), "+f"(c[1]), "+f"(c[2]), "+f"(c[3])
        : "r"(a.x), "r"(a.y), "r"(a.z), "r"(a.w), "r"(b0), "r"(b1));
}

// Dynamic smem layout (bytes).
// E rows: 128 floats permuted within 8-groups, padded to 136 floats (544 B)
// -> conflict-free LDS.64 B-fragment reads (half-warp banks 8g+2t distinct).
#define EPADB    544
#define ECHUNKB  (32 * EPADB)               // 17408
#define SM_WET   0                          // 65536: A fragments
#define SM_E0    65536
#define SM_E1    (SM_E0 + ECHUNKB)          // 82944
#define SM_ADJ   (SM_E1 + ECHUNKB)          // 100352 (256 floats)
#define SM_BEST  (SM_ADJ + 1024)            // 101376 (128 floats)
#define SM_TOTAL (SM_BEST + 512)            // 101888

// ========================================================================
// Fused aux kernel (one launch):
//   blocks [0,256)   : prep  (msg1, msg2, base)        256 threads
//   blocks [256,320) : wet   (pack We^T A-fragments)   256 threads
//   blocks [320,328) : msgg                            128 threads used
// ========================================================================
__global__ __launch_bounds__(256) void aux_kernel(
    const float* __restrict__ hidden, const float* __restrict__ nfeat,
    const float* __restrict__ gfeat,
    const float* __restrict__ W1, const float* __restrict__ b1,
    const float* __restrict__ W2, const float* __restrict__ b2,
    const float* __restrict__ We,
    const float* __restrict__ Wg, const float* __restrict__ bg,
    const float* __restrict__ Wo1, const float* __restrict__ bo1,
    const float* __restrict__ bo2)
{
    const int tid = threadIdx.x;
    if (blockIdx.x >= 320) {                       // ---- msgg ----
        if (tid < 128) {
            const int b = blockIdx.x - 320, m = tid;
            float acc = bg[m];
            #pragma unroll 8
            for (int k = 0; k < Dd; k++)
                acc = fmaf(gfeat[b * Dd + k], __ldg(&Wg[k * MIDn + m]), acc);
            g_msgg[b * MIDn + m] = acc;
        }
        return;
    }
    if (blockIdx.x >= 256) {                       // ---- wet (A pack) ----
        const int idx = (blockIdx.x - 256) * 256 + tid;   // 0..16383
        const int blk = idx >> 7;                  // fragment block
        const int mtg = blk >> 4, kt = blk & 15;
        const int l = (idx >> 2) & 31, e = idx & 3;
        const int m = mtg * 16 + (l >> 2) + (e & 1) * 8;
        const int k = kt * 8 + (l & 3) + (e >> 1) * 4;
        g_WeTpack[idx] = tf32r(We[k * MIDn + m]);
        return;
    }
    // ---- prep ----
    __shared__ float fs[8 * FEATn];
    __shared__ float red[3 * 8 * MIDn];
    const int m = tid & 127, h = tid >> 7;
    const int row0 = blockIdx.x * 8;

    for (int idx = tid; idx < 8 * FEATn; idx += 256) {
        int r = idx >> 8, c = idx & 255;
        fs[idx] = (c < Dd) ? nfeat[(row0 + r) * Dd + c]
                           : hidden[(row0 + r) * Dd + (c - Dd)];
    }
    __syncthreads();

    float a1[8], a2[8], ao[8];
    #pragma unroll
    for (int r = 0; r < 8; r++) { a1[r] = 0.f; a2[r] = 0.f; ao[r] = 0.f; }

    const int fbase = h * 128;
    #pragma unroll 4
    for (int ff = 0; ff < 128; ff++) {
        const int f = fbase + ff;
        const float w1 = __ldg(&W1[f * MIDn + m]);
        const float w2 = __ldg(&W2[f * MIDn + m]);
        const float wo = __ldg(&Wo1[f * MIDn + m]);
        #pragma unroll
        for (int r = 0; r < 8; r++) {
            const float s = fs[r * FEATn + f];
            a1[r] = fmaf(s, w1, a1[r]);
            a2[r] = fmaf(s, w2, a2[r]);
            ao[r] = fmaf(s, wo, ao[r]);
        }
    }
    if (h == 1) {
        #pragma unroll
        for (int r = 0; r < 8; r++) {
            red[0 * 1024 + r * 128 + m] = a1[r];
            red[1 * 1024 + r * 128 + m] = a2[r];
            red[2 * 1024 + r * 128 + m] = ao[r];
        }
    }
    __syncthreads();
    if (h == 0) {
        const float bb1 = b1[m], bb2 = b2[m], bbo = bo1[m] + bo2[m];
        #pragma unroll
        for (int r = 0; r < 8; r++) {
            const int row = row0 + r;
            g_msg1[row * MIDn + m] = a1[r] + red[0 * 1024 + r * 128 + m] + bb1;
            g_msg2[row * MIDn + m] = a2[r] + red[1 * 1024 + r * 128 + m] + bb2;
            g_base[row * MIDn + m] = ao[r] + red[2 * 1024 + r * 128 + m] + bbo;
        }
    }
}

// ========================================================================
// Main kernel: fused e@We + broadcast + mask + max + out GEMM (mma.sync tf32)
// CTA per (b,j). Permuted E staging: within each 8-float k-group,
// pos(k) = (k&~7) | ((k&3)<<1) | ((k>>2)&1), so B fragment pair (t, t+4)
// is one contiguous LDS.64. B fed as raw f32 bits (HW tf32 truncation).
// ========================================================================
__device__ __forceinline__ void stage_chunk(uint32_t ebuf, const float* ebj,
                                            int c, int tid)
{
    const int l = tid & 31, w = tid >> 5;
    #pragma unroll
    for (int r = 0; r < 8; r++) {
        const int i = w * 8 + r;                  // row within chunk
        const float* srow = ebj + (long)(c * 32 + i) * (Nn * Dd);
        const uint32_t drow = ebuf + i * EPADB;
        #pragma unroll
        for (int q = 0; q < 4; q++) {
            const int k = q * 32 + l;
            const int pos = (k & ~7) | ((k & 3) << 1) | ((k >> 2) & 1);
            cp4(drow + pos * 4, srow + k);
        }
    }
}

__global__ __launch_bounds__(128, 2) void main_kernel(
    const float* __restrict__ efeat, const float* __restrict__ adj,
    const float* __restrict__ be,    const float* __restrict__ Wo2,
    float* __restrict__ out)
{
    extern __shared__ __align__(16) char smem[];
    const uint32_t sb = smem_u32(smem);
    const int tid = threadIdx.x;
    const int w = tid >> 5, l = tid & 31, g = l >> 2, t = l & 3;
    const int bj = blockIdx.x, b = bj >> 8, j = bj & 255;

    const float* ebj = efeat + (long)b * (Nn * Nn * Dd) + (long)j * Dd;

    // Stage A fragments (64KB) + chunk 0 -> group 0; chunk 1 -> group 1
    for (int q = tid; q < 4096; q += 128)
        cp16(sb + SM_WET + q * 16, g_WeTpack + q * 4);
    stage_chunk(sb + SM_E0, ebj, 0, tid);
    cp_commit();
    stage_chunk(sb + SM_E1, ebj, 1, tid);
    cp_commit();

    // adj column
    float* adjs = (float*)(smem + SM_ADJ);
    for (int i = tid; i < Nn; i += 128)
        adjs[i] = adj[((long)b * Nn + i) * Nn + j];

    // per-thread constants: 4 m values (slot s: m = w*32 + (s>>1)*16 + g + (s&1)*8)
    float cst[4], best[4];
    #pragma unroll
    for (int s = 0; s < 4; s++) {
        const int m = w * 32 + (s >> 1) * 16 + g + (s & 1) * 8;
        cst[s] = g_msg1[bj * MIDn + m] + g_msgg[b * MIDn + m] + be[m];
        best[s] = -FLT_MAX;
    }

    const float* m2 = g_msg2 + ((long)b << 15);   // msg2[b]

    #pragma unroll 1
    for (int c = 0; c < 8; c++) {
        if (c < 7) { cp_wait<1>(); } else { cp_wait<0>(); }
        __syncthreads();
        const char* eb = smem + ((c & 1) ? SM_E1 : SM_E0);

        float acc[2][4][4];
        #pragma unroll
        for (int mt = 0; mt < 2; mt++)
            #pragma unroll
            for (int nt = 0; nt < 4; nt++)
                #pragma unroll
                for (int r = 0; r < 4; r++) acc[mt][nt][r] = 0.f;

        #pragma unroll
        for (int kt = 0; kt < 16; kt++) {
            const uint4 A0 = *(const uint4*)(smem + SM_WET
                              + (((w * 2 + 0) * 16 + kt) << 9) + (l << 4));
            const uint4 A1 = *(const uint4*)(smem + SM_WET
                              + (((w * 2 + 1) * 16 + kt) << 9) + (l << 4));
            #pragma unroll
            for (int nt = 0; nt < 4; nt++) {
                // pair (k=8kt+t, 8kt+t+4) contiguous after permutation
                const float2 bv = *(const float2*)(eb + (nt * 8 + g) * EPADB
                                                   + kt * 32 + t * 8);
                const unsigned b0 = __float_as_uint(bv.x);
                const unsigned b1 = __float_as_uint(bv.y);
                mma8(acc[0][nt], A0, b0, b1);
                mma8(acc[1][nt], A1, b0, b1);
            }
        }

        // fold this chunk into running max
        #pragma unroll
        for (int mt = 0; mt < 2; mt++)
            #pragma unroll
            for (int nt = 0; nt < 4; nt++) {
                const int i0 = c * 32 + nt * 8 + 2 * t;
                const float aj0 = adjs[i0], aj1 = adjs[i0 + 1];
                #pragma unroll
                for (int h = 0; h < 2; h++) {
                    const int m = w * 32 + mt * 16 + g + h * 8;
                    const int s = mt * 2 + h;
                    const float v0 = (acc[mt][nt][2 * h] + cst[s]
                                      + __ldg(m2 + (long)i0 * MIDn + m)) * aj0;
                    const float v1 = (acc[mt][nt][2 * h + 1] + cst[s]
                                      + __ldg(m2 + (long)(i0 + 1) * MIDn + m)) * aj1;
                    best[s] = fmaxf(best[s], fmaxf(v0, v1));
                }
            }
        __syncthreads();
        if (c < 6) { stage_chunk(sb + ((c & 1) ? SM_E1 : SM_E0), ebj, c + 2, tid);
                     cp_commit(); }
    }

    // reduce max across the 4 lanes of each quad
    #pragma unroll
    for (int s = 0; s < 4; s++) {
        best[s] = fmaxf(best[s], __shfl_xor_sync(0xFFFFFFFFu, best[s], 1));
        best[s] = fmaxf(best[s], __shfl_xor_sync(0xFFFFFFFFu, best[s], 2));
    }
    float* bestsm = (float*)(smem + SM_BEST);
    if (t == 0) {
        #pragma unroll
        for (int s = 0; s < 4; s++)
            bestsm[w * 32 + (s >> 1) * 16 + g + (s & 1) * 8] = best[s];
    }
    __syncthreads();

    // out = base + best @ Wo2
    float o = g_base[bj * MIDn + tid];
    #pragma unroll 8
    for (int k = 0; k < MIDn; k++)
        o = fmaf(bestsm[k], __ldg(&Wo2[(k << 7) + tid]), o);
    out[bj * MIDn + tid] = o;
}

// ========================================================================
extern "C" void kernel_launch(void* const* d_in, const int* in_sizes, int n_in,
                              void* d_out, int out_size)
{
    const float* hidden = (const float*)d_in[0];
    const float* nfeat  = (const float*)d_in[1];
    const float* efeat  = (const float*)d_in[2];
    const float* gfeat  = (const float*)d_in[3];
    const float* adj    = (const float*)d_in[4];
    const float* W1  = (const float*)d_in[5];
    const float* b1  = (const float*)d_in[6];
    const float* W2  = (const float*)d_in[7];
    const float* b2  = (const float*)d_in[8];
    const float* We  = (const float*)d_in[9];
    const float* be  = (const float*)d_in[10];
    const float* Wg  = (const float*)d_in[11];
    const float* bg  = (const float*)d_in[12];
    const float* Wo1 = (const float*)d_in[13];
    const float* bo1 = (const float*)d_in[14];
    const float* Wo2 = (const float*)d_in[15];
    const float* bo2 = (const float*)d_in[16];
    float* out = (float*)d_out;

    static int smem_set = 0;
    if (!smem_set) {
        cudaFuncSetAttribute(main_kernel,
                             cudaFuncAttributeMaxDynamicSharedMemorySize,
                             SM_TOTAL);
        smem_set = 1;
    }

    aux_kernel<<<328, 256>>>(hidden, nfeat, gfeat, W1, b1, W2, b2, We,
                             Wg, bg, Wo1, bo1, bo2);
    main_kernel<<<Bn * Nn, 128, SM_TOTAL>>>(efeat, adj, be, Wo2, out);
}

// round 6
// speedup vs baseline: 4.8078x; 1.2953x over previous
#include <cuda_runtime.h>
#include <cstdint>
#include <float.h>

// Problem constants
#define Bn    8
#define Nn    256
#define Dd    128
#define MIDn  128
#define FEATn 256   // 2*D

// Scratch (device globals; no runtime allocation allowed)
__device__ float g_msg1[Bn * Nn * MIDn];
__device__ float g_msg2[Bn * Nn * MIDn];
__device__ float g_msgg[Bn * MIDn];
__device__ float g_base[Bn * Nn * MIDn];        // features@Wo1 + bo1 + bo2
__device__ unsigned g_WeTpack[MIDn * Dd];       // We^T fragment-packed (tf32 bits)

// ---------------- PTX helpers (arch-agnostic, sm_80+) --------------------
__device__ __forceinline__ uint32_t smem_u32(const void* p) {
    uint32_t a;
    asm("{ .reg .u64 t; cvta.to.shared.u64 t, %1; cvt.u32.u64 %0, t; }"
        : "=r"(a) : "l"(p));
    return a;
}
__device__ __forceinline__ void cp16(uint32_t dst, const void* src) {
    asm volatile("cp.async.cg.shared.global [%0], [%1], 16;"
                 :: "r"(dst), "l"(src) : "memory");
}
__device__ __forceinline__ void cp_commit() {
    asm volatile("cp.async.commit_group;" ::: "memory");
}
template <int N> __device__ __forceinline__ void cp_wait() {
    asm volatile("cp.async.wait_group %0;" :: "n"(N) : "memory");
}
__device__ __forceinline__ unsigned tf32r(float x) {
    unsigned u;
    asm("cvt.rna.tf32.f32 %0, %1;" : "=r"(u) : "f"(x));
    return u;
}
// m16n8k8 tf32 HMMA
__device__ __forceinline__ void mma8(float* c, uint4 a, unsigned b0, unsigned b1) {
    asm volatile(
        "mma.sync.aligned.m16n8k8.row.col.f32.tf32.tf32.f32 "
        "{%0,%1,%2,%3},{%4,%5,%6,%7},{%8,%9},{%0,%1,%2,%3};"
        : "+f"(c[0]), "+f"(c[1]), "+f"(c[2]), "+f"(c[3])
        : "r"(a.x), "r"(a.y), "r"(a.z), "r"(a.w), "r"(b0), "r"(b1));
}

// ---------------- smem layout (bytes) ------------------------------------
// E rows natural order, padded to 136 floats (544B): LDS.64 banks 8g+2t CF.
// M2 rows padded to 132 floats (528B): LDS.32 banks 8t+g CF.
#define EPADB    544
#define ECHUNKB  (32 * EPADB)               // 17408
#define M2PADB   528
#define M2CHUNKB (32 * M2PADB)              // 16896
#define SM_E0    0
#define SM_E1    ECHUNKB                    // 17408
#define SM_M0    (2 * ECHUNKB)              // 34816
#define SM_M1    (SM_M0 + M2CHUNKB)         // 51712
#define SM_ADJ   (SM_M1 + M2CHUNKB)         // 68608 (256 floats)
#define SM_BEST  (SM_ADJ + 1024)            // 69632 (128 floats)
#define SM_TOTAL (SM_BEST + 512)            // 70144

// ========================================================================
// Fused aux kernel:
//   blocks [0,256)   : prep (msg1, msg2, base)
//   blocks [256,320) : pack We^T A-fragments (k-relabeled: lane t -> 2t,2t+1)
//   blocks [320,328) : msgg
// ========================================================================
__global__ __launch_bounds__(256) void aux_kernel(
    const float* __restrict__ hidden, const float* __restrict__ nfeat,
    const float* __restrict__ gfeat,
    const float* __restrict__ W1, const float* __restrict__ b1,
    const float* __restrict__ W2, const float* __restrict__ b2,
    const float* __restrict__ We,
    const float* __restrict__ Wg, const float* __restrict__ bg,
    const float* __restrict__ Wo1, const float* __restrict__ bo1,
    const float* __restrict__ bo2)
{
    const int tid = threadIdx.x;
    if (blockIdx.x >= 320) {                       // ---- msgg ----
        if (tid < 128) {
            const int b = blockIdx.x - 320, m = tid;
            float acc = bg[m];
            #pragma unroll 8
            for (int k = 0; k < Dd; k++)
                acc = fmaf(gfeat[b * Dd + k], __ldg(&Wg[k * MIDn + m]), acc);
            g_msgg[b * MIDn + m] = acc;
        }
        return;
    }
    if (blockIdx.x >= 256) {                       // ---- A pack ----
        const int idx = (blockIdx.x - 256) * 256 + tid;   // 0..16383
        const int blk = idx >> 7;                  // (mtg*16 + kt)
        const int mtg = blk >> 4, kt = blk & 15;
        const int l = (idx >> 2) & 31, e = idx & 3;
        const int m = mtg * 16 + (l >> 2) + (e & 1) * 8;
        // k-relabel: ISA k-slot t holds physical k = 2t, k-slot t+4 -> 2t+1
        const int k = kt * 8 + 2 * (l & 3) + (e >> 1);
        g_WeTpack[idx] = tf32r(We[k * MIDn + m]);
        return;
    }
    // ---- prep ----
    __shared__ float fs[8 * FEATn];
    __shared__ float red[3 * 8 * MIDn];
    const int m = tid & 127, h = tid >> 7;
    const int row0 = blockIdx.x * 8;

    for (int idx = tid; idx < 8 * FEATn; idx += 256) {
        int r = idx >> 8, c = idx & 255;
        fs[idx] = (c < Dd) ? nfeat[(row0 + r) * Dd + c]
                           : hidden[(row0 + r) * Dd + (c - Dd)];
    }
    __syncthreads();

    float a1[8], a2[8], ao[8];
    #pragma unroll
    for (int r = 0; r < 8; r++) { a1[r] = 0.f; a2[r] = 0.f; ao[r] = 0.f; }

    const int fbase = h * 128;
    #pragma unroll 4
    for (int ff = 0; ff < 128; ff++) {
        const int f = fbase + ff;
        const float w1 = __ldg(&W1[f * MIDn + m]);
        const float w2 = __ldg(&W2[f * MIDn + m]);
        const float wo = __ldg(&Wo1[f * MIDn + m]);
        #pragma unroll
        for (int r = 0; r < 8; r++) {
            const float s = fs[r * FEATn + f];
            a1[r] = fmaf(s, w1, a1[r]);
            a2[r] = fmaf(s, w2, a2[r]);
            ao[r] = fmaf(s, wo, ao[r]);
        }
    }
    if (h == 1) {
        #pragma unroll
        for (int r = 0; r < 8; r++) {
            red[0 * 1024 + r * 128 + m] = a1[r];
            red[1 * 1024 + r * 128 + m] = a2[r];
            red[2 * 1024 + r * 128 + m] = ao[r];
        }
    }
    __syncthreads();
    if (h == 0) {
        const float bb1 = b1[m], bb2 = b2[m], bbo = bo1[m] + bo2[m];
        #pragma unroll
        for (int r = 0; r < 8; r++) {
            const int row = row0 + r;
            g_msg1[row * MIDn + m] = a1[r] + red[0 * 1024 + r * 128 + m] + bb1;
            g_msg2[row * MIDn + m] = a2[r] + red[1 * 1024 + r * 128 + m] + bb2;
            g_base[row * MIDn + m] = ao[r] + red[2 * 1024 + r * 128 + m] + bbo;
        }
    }
}

// ========================================================================
// Main kernel: CTA per (b,j). A (We^T) in registers; E + msg2 chunks
// double-buffered through smem via cp16; B from natural layout via LDS.64
// (k-relabeled); masked max in regs; out = base + best@Wo2.
// ========================================================================
__device__ __forceinline__ void stage_chunk(uint32_t sb, const float* ebj,
                                            const float* m2g, int c,
                                            int w, int l)
{
    const uint32_t ebuf = sb + ((c & 1) ? SM_E1 : SM_E0);
    const uint32_t mbuf = sb + ((c & 1) ? SM_M1 : SM_M0);
    #pragma unroll
    for (int rr = 0; rr < 8; rr++) {
        const int r = w + rr * 4;                 // 0..31 row within chunk
        const long i = c * 32 + r;
        cp16(ebuf + r * EPADB + l * 16, ebj + i * (Nn * Dd) + l * 4);
        cp16(mbuf + r * M2PADB + l * 16, m2g + i * MIDn + l * 4);
    }
}

__global__ __launch_bounds__(128, 2) void main_kernel(
    const float* __restrict__ efeat, const float* __restrict__ adj,
    const float* __restrict__ be,    const float* __restrict__ Wo2,
    float* __restrict__ out)
{
    extern __shared__ __align__(16) char smem[];
    const uint32_t sb = smem_u32(smem);
    const int tid = threadIdx.x;
    const int w = tid >> 5, l = tid & 31, g = l >> 2, t = l & 3;
    const int bj = blockIdx.x, b = bj >> 8, j = bj & 255;

    const float* ebj = efeat + (long)b * (Nn * Nn * Dd) + (long)j * Dd;
    const float* m2g = g_msg2 + ((long)b << 15);

    // A fragments -> registers (one-time, coalesced LDG.128)
    uint4 A[2][16];
    #pragma unroll
    for (int mt = 0; mt < 2; mt++)
        #pragma unroll
        for (int kt = 0; kt < 16; kt++)
            A[mt][kt] = *(const uint4*)(g_WeTpack
                         + (((w * 2 + mt) * 16 + kt) << 7) + (l << 2));

    // Prefill pipeline: chunks 0 and 1
    stage_chunk(sb, ebj, m2g, 0, w, l);
    cp_commit();
    stage_chunk(sb, ebj, m2g, 1, w, l);
    cp_commit();

    // adj column
    float* adjs = (float*)(smem + SM_ADJ);
    for (int i = tid; i < Nn; i += 128)
        adjs[i] = adj[((long)b * Nn + i) * Nn + j];

    // constants: slot s -> m = w*32 + (s>>1)*16 + g + (s&1)*8
    float cst[4], best[4];
    #pragma unroll
    for (int s = 0; s < 4; s++) {
        const int m = w * 32 + (s >> 1) * 16 + g + (s & 1) * 8;
        cst[s] = g_msg1[bj * MIDn + m] + g_msgg[b * MIDn + m] + be[m];
        best[s] = -FLT_MAX;
    }

    #pragma unroll 1
    for (int c = 0; c < 8; c++) {
        if (c < 7) { cp_wait<1>(); } else { cp_wait<0>(); }
        __syncthreads();
        const char* eb = smem + ((c & 1) ? SM_E1 : SM_E0);
        const float* m2s = (const float*)(smem + ((c & 1) ? SM_M1 : SM_M0));

        float acc[2][4][4];
        #pragma unroll
        for (int mt = 0; mt < 2; mt++)
            #pragma unroll
            for (int nt = 0; nt < 4; nt++)
                #pragma unroll
                for (int r = 0; r < 4; r++) acc[mt][nt][r] = 0.f;

        #pragma unroll
        for (int kt = 0; kt < 16; kt++) {
            #pragma unroll
            for (int nt = 0; nt < 4; nt++) {
                // physical k pair (8kt+2t, 8kt+2t+1): contiguous LDS.64
                const float2 bv = *(const float2*)(eb + (nt * 8 + g) * EPADB
                                                   + kt * 32 + t * 8);
                const unsigned b0 = __float_as_uint(bv.x);
                const unsigned b1 = __float_as_uint(bv.y);
                mma8(acc[0][nt], A[0][kt], b0, b1);
                mma8(acc[1][nt], A[1][kt], b0, b1);
            }
        }

        // fold chunk into running max (m2 from smem)
        #pragma unroll
        for (int nt = 0; nt < 4; nt++) {
            const int il = nt * 8 + 2 * t;              // local i
            const float aj0 = adjs[c * 32 + il];
            const float aj1 = adjs[c * 32 + il + 1];
            const int mwg = w * 32 + g;
            #pragma unroll
            for (int mt = 0; mt < 2; mt++)
                #pragma unroll
                for (int h = 0; h < 2; h++) {
                    const int m = mwg + mt * 16 + h * 8;
                    const int s = mt * 2 + h;
                    const float v0 = (acc[mt][nt][2 * h] + cst[s]
                                      + m2s[il * 132 + m]) * aj0;
                    const float v1 = (acc[mt][nt][2 * h + 1] + cst[s]
                                      + m2s[(il + 1) * 132 + m]) * aj1;
                    best[s] = fmaxf(best[s], fmaxf(v0, v1));
                }
        }
        __syncthreads();
        if (c < 6) { stage_chunk(sb, ebj, m2g, c + 2, w, l); cp_commit(); }
    }

    // reduce max across the 4 lanes of each quad
    #pragma unroll
    for (int s = 0; s < 4; s++) {
        best[s] = fmaxf(best[s], __shfl_xor_sync(0xFFFFFFFFu, best[s], 1));
        best[s] = fmaxf(best[s], __shfl_xor_sync(0xFFFFFFFFu, best[s], 2));
    }
    float* bestsm = (float*)(smem + SM_BEST);
    if (t == 0) {
        #pragma unroll
        for (int s = 0; s < 4; s++)
            bestsm[w * 32 + (s >> 1) * 16 + g + (s & 1) * 8] = best[s];
    }
    __syncthreads();

    // out = base + best @ Wo2
    float o = g_base[bj * MIDn + tid];
    #pragma unroll 8
    for (int k = 0; k < MIDn; k++)
        o = fmaf(bestsm[k], __ldg(&Wo2[(k << 7) + tid]), o);
    out[bj * MIDn + tid] = o;
}

// ========================================================================
extern "C" void kernel_launch(void* const* d_in, const int* in_sizes, int n_in,
                              void* d_out, int out_size)
{
    const float* hidden = (const float*)d_in[0];
    const float* nfeat  = (const float*)d_in[1];
    const float* efeat  = (const float*)d_in[2];
    const float* gfeat  = (const float*)d_in[3];
    const float* adj    = (const float*)d_in[4];
    const float* W1  = (const float*)d_in[5];
    const float* b1  = (const float*)d_in[6];
    const float* W2  = (const float*)d_in[7];
    const float* b2  = (const float*)d_in[8];
    const float* We  = (const float*)d_in[9];
    const float* be  = (const float*)d_in[10];
    const float* Wg  = (const float*)d_in[11];
    const float* bg  = (const float*)d_in[12];
    const float* Wo1 = (const float*)d_in[13];
    const float* bo1 = (const float*)d_in[14];
    const float* Wo2 = (const float*)d_in[15];
    const float* bo2 = (const float*)d_in[16];
    float* out = (float*)d_out;

    static int smem_set = 0;
    if (!smem_set) {
        cudaFuncSetAttribute(main_kernel,
                             cudaFuncAttributeMaxDynamicSharedMemorySize,
                             SM_TOTAL);
        smem_set = 1;
    }

    aux_kernel<<<328, 256>>>(hidden, nfeat, gfeat, W1, b1, W2, b2, We,
                             Wg, bg, Wo1, bo1, bo2);
    main_kernel<<<Bn * Nn, 128, SM_TOTAL>>>(efeat, adj, be, Wo2, out);
}

// round 7
// speedup vs baseline: 5.9287x; 1.2331x over previous
#include <cuda_runtime.h>
#include <cstdint>
#include <float.h>

// Problem constants
#define Bn    8
#define Nn    256
#define Dd    128
#define MIDn  128
#define FEATn 256   // 2*D

// Scratch (device globals; no runtime allocation allowed)
__device__ float g_msg1[Bn * Nn * MIDn];
__device__ float g_msg2[Bn * Nn * MIDn];
__device__ float g_msgg[Bn * MIDn];
__device__ float g_base[Bn * Nn * MIDn];        // features@Wo1 + bo1 + bo2
__device__ unsigned g_WeTpack[MIDn * Dd];       // We^T fragment-packed (tf32 bits)

// ---------------- PTX helpers (arch-agnostic, sm_80+) --------------------
__device__ __forceinline__ uint32_t smem_u32(const void* p) {
    uint32_t a;
    asm("{ .reg .u64 t; cvta.to.shared.u64 t, %1; cvt.u32.u64 %0, t; }"
        : "=r"(a) : "l"(p));
    return a;
}
__device__ __forceinline__ void cp16(uint32_t dst, const void* src) {
    asm volatile("cp.async.cg.shared.global [%0], [%1], 16;"
                 :: "r"(dst), "l"(src) : "memory");
}
__device__ __forceinline__ void cp_commit() {
    asm volatile("cp.async.commit_group;" ::: "memory");
}
template <int N> __device__ __forceinline__ void cp_wait() {
    asm volatile("cp.async.wait_group %0;" :: "n"(N) : "memory");
}
__device__ __forceinline__ unsigned tf32r(float x) {
    unsigned u;
    asm("cvt.rna.tf32.f32 %0, %1;" : "=r"(u) : "f"(x));
    return u;
}
// m16n8k8 tf32 HMMA
__device__ __forceinline__ void mma8(float* c, uint4 a, unsigned b0, unsigned b1) {
    asm volatile(
        "mma.sync.aligned.m16n8k8.row.col.f32.tf32.tf32.f32 "
        "{%0,%1,%2,%3},{%4,%5,%6,%7},{%8,%9},{%0,%1,%2,%3};"
        : "+f"(c[0]), "+f"(c[1]), "+f"(c[2]), "+f"(c[3])
        : "r"(a.x), "r"(a.y), "r"(a.z), "r"(a.w), "r"(b0), "r"(b1));
}

// ---------------- smem layout (bytes) ------------------------------------
#define EPADB    544                        // 136 floats: LDS.64 CF
#define ECHUNKB  (32 * EPADB)               // 17408
#define M2PADB   528                        // 132 floats: LDS.32 CF
#define M2CHUNKB (32 * M2PADB)              // 16896
#define SM_E0    0
#define SM_E1    ECHUNKB
#define SM_M0    (2 * ECHUNKB)              // 34816
#define SM_M1    (SM_M0 + M2CHUNKB)         // 51712
#define SM_IDX   (SM_M1 + M2CHUNKB)         // 68608  (256 ints)
#define SM_CNT   (SM_IDX + 1024)            // 69632
#define SM_BEST  (SM_CNT + 128)             // 69760  (128 floats)
#define SM_TOTAL (SM_BEST + 512)            // 70272

// ========================================================================
// Fused aux kernel:
//   blocks [0,256)   : prep (msg1, msg2, base)
//   blocks [256,320) : pack We^T A-fragments (k-relabel: slot t -> 2t,2t+1)
//   blocks [320,328) : msgg
// ========================================================================
__global__ __launch_bounds__(256) void aux_kernel(
    const float* __restrict__ hidden, const float* __restrict__ nfeat,
    const float* __restrict__ gfeat,
    const float* __restrict__ W1, const float* __restrict__ b1,
    const float* __restrict__ W2, const float* __restrict__ b2,
    const float* __restrict__ We,
    const float* __restrict__ Wg, const float* __restrict__ bg,
    const float* __restrict__ Wo1, const float* __restrict__ bo1,
    const float* __restrict__ bo2)
{
    const int tid = threadIdx.x;
    if (blockIdx.x >= 320) {                       // ---- msgg ----
        if (tid < 128) {
            const int b = blockIdx.x - 320, m = tid;
            float acc = bg[m];
            #pragma unroll 8
            for (int k = 0; k < Dd; k++)
                acc = fmaf(gfeat[b * Dd + k], __ldg(&Wg[k * MIDn + m]), acc);
            g_msgg[b * MIDn + m] = acc;
        }
        return;
    }
    if (blockIdx.x >= 256) {                       // ---- A pack ----
        const int idx = (blockIdx.x - 256) * 256 + tid;   // 0..16383
        const int blk = idx >> 7;
        const int mtg = blk >> 4, kt = blk & 15;
        const int l = (idx >> 2) & 31, e = idx & 3;
        const int m = mtg * 16 + (l >> 2) + (e & 1) * 8;
        const int k = kt * 8 + 2 * (l & 3) + (e >> 1);
        g_WeTpack[idx] = tf32r(We[k * MIDn + m]);
        return;
    }
    // ---- prep ----
    __shared__ float fs[8 * FEATn];
    __shared__ float red[3 * 8 * MIDn];
    const int m = tid & 127, h = tid >> 7;
    const int row0 = blockIdx.x * 8;

    for (int idx = tid; idx < 8 * FEATn; idx += 256) {
        int r = idx >> 8, c = idx & 255;
        fs[idx] = (c < Dd) ? nfeat[(row0 + r) * Dd + c]
                           : hidden[(row0 + r) * Dd + (c - Dd)];
    }
    __syncthreads();

    float a1[8], a2[8], ao[8];
    #pragma unroll
    for (int r = 0; r < 8; r++) { a1[r] = 0.f; a2[r] = 0.f; ao[r] = 0.f; }

    const int fbase = h * 128;
    #pragma unroll 4
    for (int ff = 0; ff < 128; ff++) {
        const int f = fbase + ff;
        const float w1 = __ldg(&W1[f * MIDn + m]);
        const float w2 = __ldg(&W2[f * MIDn + m]);
        const float wo = __ldg(&Wo1[f * MIDn + m]);
        #pragma unroll
        for (int r = 0; r < 8; r++) {
            const float s = fs[r * FEATn + f];
            a1[r] = fmaf(s, w1, a1[r]);
            a2[r] = fmaf(s, w2, a2[r]);
            ao[r] = fmaf(s, wo, ao[r]);
        }
    }
    if (h == 1) {
        #pragma unroll
        for (int r = 0; r < 8; r++) {
            red[0 * 1024 + r * 128 + m] = a1[r];
            red[1 * 1024 + r * 128 + m] = a2[r];
            red[2 * 1024 + r * 128 + m] = ao[r];
        }
    }
    __syncthreads();
    if (h == 0) {
        const float bb1 = b1[m], bb2 = b2[m], bbo = bo1[m] + bo2[m];
        #pragma unroll
        for (int r = 0; r < 8; r++) {
            const int row = row0 + r;
            g_msg1[row * MIDn + m] = a1[r] + red[0 * 1024 + r * 128 + m] + bb1;
            g_msg2[row * MIDn + m] = a2[r] + red[1 * 1024 + r * 128 + m] + bb2;
            g_base[row * MIDn + m] = ao[r] + red[2 * 1024 + r * 128 + m] + bbo;
        }
    }
}

// ========================================================================
// Main kernel (sparse): CTA per (b,j). Compact neighbor list (adj!=0),
// gather only those E/msg2 rows, GEMM+max over the compact set, then
// clamp with 0 iff any adj==0. Exact vs reference.
// ========================================================================
__device__ __forceinline__ void stage_chunk(uint32_t sb, const float* ebj,
                                            const float* m2g,
                                            const int* idxsm, int c,
                                            int w, int l)
{
    const uint32_t ebuf = sb + ((c & 1) ? SM_E1 : SM_E0);
    const uint32_t mbuf = sb + ((c & 1) ? SM_M1 : SM_M0);
    #pragma unroll
    for (int rr = 0; rr < 8; rr++) {
        const int r = w + rr * 4;                 // slot within chunk 0..31
        const long i = idxsm[c * 32 + r];         // gathered row
        cp16(ebuf + r * EPADB + l * 16, ebj + i * (Nn * Dd) + l * 4);
        cp16(mbuf + r * M2PADB + l * 16, m2g + i * MIDn + l * 4);
    }
}

__global__ __launch_bounds__(128, 2) void main_kernel(
    const float* __restrict__ efeat, const float* __restrict__ adj,
    const float* __restrict__ be,    const float* __restrict__ Wo2,
    float* __restrict__ out)
{
    extern __shared__ __align__(16) char smem[];
    const uint32_t sb = smem_u32(smem);
    const int tid = threadIdx.x;
    const int w = tid >> 5, l = tid & 31, g = l >> 2, t = l & 3;
    const int bj = blockIdx.x, b = bj >> 8, j = bj & 255;

    const float* ebj = efeat + (long)b * (Nn * Nn * Dd) + (long)j * Dd;
    const float* m2g = g_msg2 + ((long)b << 15);
    int* idxsm = (int*)(smem + SM_IDX);
    int* cntp  = (int*)(smem + SM_CNT);

    if (tid == 0) *cntp = 0;

    // A fragments -> registers (one-time, coalesced LDG.128)
    uint4 A[2][16];
    #pragma unroll
    for (int mt = 0; mt < 2; mt++)
        #pragma unroll
        for (int kt = 0; kt < 16; kt++)
            A[mt][kt] = *(const uint4*)(g_WeTpack
                         + (((w * 2 + mt) * 16 + kt) << 7) + (l << 2));
    __syncthreads();

    // --- build compact neighbor list via warp ballots ---
    #pragma unroll
    for (int pp = 0; pp < 2; pp++) {
        const int p = w * 2 + pp;                 // pass 0..7
        const int i = p * 32 + l;
        const float a = adj[((long)b * Nn + i) * Nn + j];
        const unsigned mask = __ballot_sync(0xFFFFFFFFu, a != 0.f);
        int basep = 0;
        if (l == 0) basep = atomicAdd(cntp, __popc(mask));
        basep = __shfl_sync(0xFFFFFFFFu, basep, 0);
        if (a != 0.f)
            idxsm[basep + __popc(mask & ((1u << l) - 1))] = i;
    }
    __syncthreads();
    const int cnt = *cntp;
    const int nc = (cnt + 31) >> 5;
    for (int s = cnt + tid; s < 256; s += 128) idxsm[s] = 0;   // pads
    __syncthreads();

    // Prefill pipeline
    if (nc > 0) stage_chunk(sb, ebj, m2g, idxsm, 0, w, l);
    cp_commit();
    if (nc > 1) stage_chunk(sb, ebj, m2g, idxsm, 1, w, l);
    cp_commit();

    // constants: slot s -> m = w*32 + (s>>1)*16 + g + (s&1)*8
    float cst[4], best[4];
    #pragma unroll
    for (int s = 0; s < 4; s++) {
        const int m = w * 32 + (s >> 1) * 16 + g + (s & 1) * 8;
        cst[s] = g_msg1[bj * MIDn + m] + g_msgg[b * MIDn + m] + be[m];
        best[s] = -FLT_MAX;
    }

    #pragma unroll 1
    for (int c = 0; c < nc; c++) {
        cp_wait<1>();
        __syncthreads();
        const char* eb = smem + ((c & 1) ? SM_E1 : SM_E0);
        const float* m2s = (const float*)(smem + ((c & 1) ? SM_M1 : SM_M0));

        float acc[2][4][4];
        #pragma unroll
        for (int mt = 0; mt < 2; mt++)
            #pragma unroll
            for (int nt = 0; nt < 4; nt++)
                #pragma unroll
                for (int r = 0; r < 4; r++) acc[mt][nt][r] = 0.f;

        #pragma unroll
        for (int kt = 0; kt < 16; kt++) {
            #pragma unroll
            for (int nt = 0; nt < 4; nt++) {
                const float2 bv = *(const float2*)(eb + (nt * 8 + g) * EPADB
                                                   + kt * 32 + t * 8);
                const unsigned b0 = __float_as_uint(bv.x);
                const unsigned b1 = __float_as_uint(bv.y);
                mma8(acc[0][nt], A[0][kt], b0, b1);
                mma8(acc[1][nt], A[1][kt], b0, b1);
            }
        }

        // fold: mask pad slots (slot >= cnt contributes 0; safe since
        // pads exist only when cnt < 256, where the 0-clamp applies)
        #pragma unroll
        for (int nt = 0; nt < 4; nt++) {
            const int il = nt * 8 + 2 * t;
            const int slot = c * 32 + il;
            const float aj0 = (slot < cnt) ? 1.f : 0.f;
            const float aj1 = (slot + 1 < cnt) ? 1.f : 0.f;
            const int mwg = w * 32 + g;
            #pragma unroll
            for (int mt = 0; mt < 2; mt++)
                #pragma unroll
                for (int h = 0; h < 2; h++) {
                    const int m = mwg + mt * 16 + h * 8;
                    const int s = mt * 2 + h;
                    const float v0 = (acc[mt][nt][2 * h] + cst[s]
                                      + m2s[il * 132 + m]) * aj0;
                    const float v1 = (acc[mt][nt][2 * h + 1] + cst[s]
                                      + m2s[(il + 1) * 132 + m]) * aj1;
                    best[s] = fmaxf(best[s], fmaxf(v0, v1));
                }
        }
        __syncthreads();
        if (c + 2 < nc) stage_chunk(sb, ebj, m2g, idxsm, c + 2, w, l);
        cp_commit();
    }

    // clamp with 0 iff at least one adj==0 (also covers cnt==0)
    if (cnt < Nn) {
        #pragma unroll
        for (int s = 0; s < 4; s++) best[s] = fmaxf(best[s], 0.f);
    }

    // reduce max across the 4 lanes of each quad
    #pragma unroll
    for (int s = 0; s < 4; s++) {
        best[s] = fmaxf(best[s], __shfl_xor_sync(0xFFFFFFFFu, best[s], 1));
        best[s] = fmaxf(best[s], __shfl_xor_sync(0xFFFFFFFFu, best[s], 2));
    }
    float* bestsm = (float*)(smem + SM_BEST);
    if (t == 0) {
        #pragma unroll
        for (int s = 0; s < 4; s++)
            bestsm[w * 32 + (s >> 1) * 16 + g + (s & 1) * 8] = best[s];
    }
    __syncthreads();

    // out = base + best @ Wo2
    float o = g_base[bj * MIDn + tid];
    #pragma unroll 8
    for (int k = 0; k < MIDn; k++)
        o = fmaf(bestsm[k], __ldg(&Wo2[(k << 7) + tid]), o);
    out[bj * MIDn + tid] = o;
}

// ========================================================================
extern "C" void kernel_launch(void* const* d_in, const int* in_sizes, int n_in,
                              void* d_out, int out_size)
{
    const float* hidden = (const float*)d_in[0];
    const float* nfeat  = (const float*)d_in[1];
    const float* efeat  = (const float*)d_in[2];
    const float* gfeat  = (const float*)d_in[3];
    const float* adj    = (const float*)d_in[4];
    const float* W1  = (const float*)d_in[5];
    const float* b1  = (const float*)d_in[6];
    const float* W2  = (const float*)d_in[7];
    const float* b2  = (const float*)d_in[8];
    const float* We  = (const float*)d_in[9];
    const float* be  = (const float*)d_in[10];
    const float* Wg  = (const float*)d_in[11];
    const float* bg  = (const float*)d_in[12];
    const float* Wo1 = (const float*)d_in[13];
    const float* bo1 = (const float*)d_in[14];
    const float* Wo2 = (const float*)d_in[15];
    const float* bo2 = (const float*)d_in[16];
    float* out = (float*)d_out;

    static int smem_set = 0;
    if (!smem_set) {
        cudaFuncSetAttribute(main_kernel,
                             cudaFuncAttributeMaxDynamicSharedMemorySize,
                             SM_TOTAL);
        smem_set = 1;
    }

    aux_kernel<<<328, 256>>>(hidden, nfeat, gfeat, W1, b1, W2, b2, We,
                             Wg, bg, Wo1, bo1, bo2);
    main_kernel<<<Bn * Nn, 128, SM_TOTAL>>>(efeat, adj, be, Wo2, out);
}

// round 8
// speedup vs baseline: 6.6110x; 1.1151x over previous
#include <cuda_runtime.h>
#include <cstdint>
#include <float.h>

// Problem constants
#define Bn    8
#define Nn    256
#define Dd    128
#define MIDn  128
#define FEATn 256   // 2*D
#define NTOT  (Bn * Nn)     // 2048 (b,j) tiles
#define GRID  296           // persistent: 2 CTAs x 148 SMs

// Scratch (device globals; no runtime allocation allowed)
__device__ float g_msg1[Bn * Nn * MIDn];
__device__ float g_msg2[Bn * Nn * MIDn];
__device__ float g_msgg[Bn * MIDn];
__device__ float g_base[Bn * Nn * MIDn];
__device__ unsigned g_WeTpack[MIDn * Dd];       // We^T fragment-packed (tf32 bits)

// ---------------- PTX helpers (arch-agnostic, sm_80+) --------------------
__device__ __forceinline__ uint32_t smem_u32(const void* p) {
    uint32_t a;
    asm("{ .reg .u64 t; cvta.to.shared.u64 t, %1; cvt.u32.u64 %0, t; }"
        : "=r"(a) : "l"(p));
    return a;
}
__device__ __forceinline__ void cp16(uint32_t dst, const void* src) {
    asm volatile("cp.async.cg.shared.global [%0], [%1], 16;"
                 :: "r"(dst), "l"(src) : "memory");
}
__device__ __forceinline__ void cp_commit() {
    asm volatile("cp.async.commit_group;" ::: "memory");
}
template <int N> __device__ __forceinline__ void cp_wait() {
    asm volatile("cp.async.wait_group %0;" :: "n"(N) : "memory");
}
__device__ __forceinline__ unsigned tf32r(float x) {
    unsigned u;
    asm("cvt.rna.tf32.f32 %0, %1;" : "=r"(u) : "f"(x));
    return u;
}
__device__ __forceinline__ void mma8(float* c, uint4 a, unsigned b0, unsigned b1) {
    asm volatile(
        "mma.sync.aligned.m16n8k8.row.col.f32.tf32.tf32.f32 "
        "{%0,%1,%2,%3},{%4,%5,%6,%7},{%8,%9},{%0,%1,%2,%3};"
        : "+f"(c[0]), "+f"(c[1]), "+f"(c[2]), "+f"(c[3])
        : "r"(a.x), "r"(a.y), "r"(a.z), "r"(a.w), "r"(b0), "r"(b1));
}

// ---------------- smem layout (bytes) ------------------------------------
#define EPADB    544                        // 136 floats: LDS.64 CF
#define ECHUNKB  (32 * EPADB)               // 17408
#define M2PADB   528                        // 132 floats: LDS.32 CF
#define M2CHUNKB (32 * M2PADB)              // 16896
#define SM_E0    0
#define SM_E1    ECHUNKB
#define SM_M0    (2 * ECHUNKB)              // 34816
#define SM_M1    (SM_M0 + M2CHUNKB)         // 51712
#define SM_IDX0  (SM_M1 + M2CHUNKB)         // 68608 (256 ints)
#define SM_IDX1  (SM_IDX0 + 1024)           // 69632 (256 ints)
#define SM_CNT0  (SM_IDX1 + 1024)           // 70656
#define SM_CNT1  (SM_CNT0 + 4)
#define SM_BEST  (SM_CNT1 + 124)            // 70784 (128 floats)
#define SM_TOTAL (SM_BEST + 512)            // 71296

// ========================================================================
// Fused aux kernel (512 threads/block, 296 blocks):
//   [0,256)   : prep (msg1,msg2,base)  m=tid&127, f-quarter h=tid>>7
//   [256,288) : pack We^T A-fragments  (k-relabel: slot t -> 2t,2t+1)
//   [288,296) : msgg (tid<128)
// ========================================================================
__global__ __launch_bounds__(512) void aux_kernel(
    const float* __restrict__ hidden, const float* __restrict__ nfeat,
    const float* __restrict__ gfeat,
    const float* __restrict__ W1, const float* __restrict__ b1,
    const float* __restrict__ W2, const float* __restrict__ b2,
    const float* __restrict__ We,
    const float* __restrict__ Wg, const float* __restrict__ bg,
    const float* __restrict__ Wo1, const float* __restrict__ bo1,
    const float* __restrict__ bo2)
{
    const int tid = threadIdx.x;
    if (blockIdx.x >= 288) {                       // ---- msgg ----
        if (tid < 128) {
            const int b = blockIdx.x - 288, m = tid;
            float acc = bg[m];
            #pragma unroll 8
            for (int k = 0; k < Dd; k++)
                acc = fmaf(gfeat[b * Dd + k], __ldg(&Wg[k * MIDn + m]), acc);
            g_msgg[b * MIDn + m] = acc;
        }
        return;
    }
    if (blockIdx.x >= 256) {                       // ---- A pack ----
        const int idx = (blockIdx.x - 256) * 512 + tid;   // 0..16383
        const int blk = idx >> 7;
        const int mtg = blk >> 4, kt = blk & 15;
        const int l = (idx >> 2) & 31, e = idx & 3;
        const int m = mtg * 16 + (l >> 2) + (e & 1) * 8;
        const int k = kt * 8 + 2 * (l & 3) + (e >> 1);
        g_WeTpack[idx] = tf32r(We[k * MIDn + m]);
        return;
    }
    // ---- prep: 8 rows, f split 4 ways ----
    __shared__ float fs[8 * FEATn];
    __shared__ float red[3][3 * 1024];             // partials for h=1,2,3
    const int m = tid & 127, h = tid >> 7;         // h in 0..3
    const int row0 = blockIdx.x * 8;

    for (int idx = tid; idx < 8 * FEATn; idx += 512) {
        int r = idx >> 8, c = idx & 255;
        fs[idx] = (c < Dd) ? nfeat[(row0 + r) * Dd + c]
                           : hidden[(row0 + r) * Dd + (c - Dd)];
    }
    __syncthreads();

    float a1[8], a2[8], ao[8];
    #pragma unroll
    for (int r = 0; r < 8; r++) { a1[r] = 0.f; a2[r] = 0.f; ao[r] = 0.f; }

    const int fbase = h * 64;
    #pragma unroll 4
    for (int ff = 0; ff < 64; ff++) {
        const int f = fbase + ff;
        const float w1 = __ldg(&W1[f * MIDn + m]);
        const float w2 = __ldg(&W2[f * MIDn + m]);
        const float wo = __ldg(&Wo1[f * MIDn + m]);
        #pragma unroll
        for (int r = 0; r < 8; r++) {
            const float s = fs[r * FEATn + f];
            a1[r] = fmaf(s, w1, a1[r]);
            a2[r] = fmaf(s, w2, a2[r]);
            ao[r] = fmaf(s, wo, ao[r]);
        }
    }
    if (h > 0) {
        #pragma unroll
        for (int r = 0; r < 8; r++) {
            red[h - 1][0 * 1024 + r * 128 + m] = a1[r];
            red[h - 1][1 * 1024 + r * 128 + m] = a2[r];
            red[h - 1][2 * 1024 + r * 128 + m] = ao[r];
        }
    }
    __syncthreads();
    if (h == 0) {
        const float bb1 = b1[m], bb2 = b2[m], bbo = bo1[m] + bo2[m];
        #pragma unroll
        for (int r = 0; r < 8; r++) {
            const int row = row0 + r;
            const int o = r * 128 + m;
            g_msg1[row * MIDn + m] = a1[r] + red[0][o] + red[1][o]
                                   + red[2][o] + bb1;
            g_msg2[row * MIDn + m] = a2[r] + red[0][1024 + o] + red[1][1024 + o]
                                   + red[2][1024 + o] + bb2;
            g_base[row * MIDn + m] = ao[r] + red[0][2048 + o] + red[1][2048 + o]
                                   + red[2][2048 + o] + bbo;
        }
    }
}

// ========================================================================
// Persistent main kernel: CTA loops over (b,j) tiles stride GRID.
// Per tile: compact neighbor list, gather E/msg2 chunks (double-buffered),
// tf32 mma, masked max, 0-clamp iff any adj==0, out = base + best@Wo2.
// Next tile's list+prefill issued BEFORE current epilogue (overlap).
// ========================================================================
__device__ __forceinline__ void stage_chunk(uint32_t sb, const float* ebj,
                                            const float* m2g,
                                            const int* idxsm, int c,
                                            int w, int l)
{
    const uint32_t ebuf = sb + ((c & 1) ? SM_E1 : SM_E0);
    const uint32_t mbuf = sb + ((c & 1) ? SM_M1 : SM_M0);
    #pragma unroll
    for (int rr = 0; rr < 8; rr++) {
        const int r = w + rr * 4;
        const long i = idxsm[c * 32 + r];
        cp16(ebuf + r * EPADB + l * 16, ebj + i * (Nn * Dd) + l * 4);
        cp16(mbuf + r * M2PADB + l * 16, m2g + i * MIDn + l * 4);
    }
}

__device__ __forceinline__ int build_list(const float* __restrict__ adjcol,
                                          int* idxd, int* cntd,
                                          int tid, int w, int l)
{
    if (tid == 0) *cntd = 0;
    __syncthreads();
    #pragma unroll
    for (int pp = 0; pp < 2; pp++) {
        const int i = (w * 2 + pp) * 32 + l;
        const float a = adjcol[(long)i * Nn];
        const unsigned mask = __ballot_sync(0xFFFFFFFFu, a != 0.f);
        int basep = 0;
        if (l == 0) basep = atomicAdd(cntd, __popc(mask));
        basep = __shfl_sync(0xFFFFFFFFu, basep, 0);
        if (a != 0.f) idxd[basep + __popc(mask & ((1u << l) - 1))] = i;
    }
    __syncthreads();
    const int cnt = *cntd;
    for (int s = cnt + tid; s < 256; s += 128) idxd[s] = 0;   // pads
    __syncthreads();
    return cnt;
}

__global__ __launch_bounds__(128, 2) void main_kernel(
    const float* __restrict__ efeat, const float* __restrict__ adj,
    const float* __restrict__ be,    const float* __restrict__ Wo2,
    float* __restrict__ out)
{
    extern __shared__ __align__(16) char smem[];
    const uint32_t sb = smem_u32(smem);
    const int tid = threadIdx.x;
    const int w = tid >> 5, l = tid & 31, g = l >> 2, t = l & 3;

    int* idxb[2] = { (int*)(smem + SM_IDX0), (int*)(smem + SM_IDX1) };
    int* cntb[2] = { (int*)(smem + SM_CNT0), (int*)(smem + SM_CNT1) };
    float* bestsm = (float*)(smem + SM_BEST);

    // A fragments -> registers, once per CTA lifetime
    uint4 A[2][16];
    #pragma unroll
    for (int mt = 0; mt < 2; mt++)
        #pragma unroll
        for (int kt = 0; kt < 16; kt++)
            A[mt][kt] = *(const uint4*)(g_WeTpack
                         + (((w * 2 + mt) * 16 + kt) << 7) + (l << 2));

    int it = blockIdx.x;
    int buf = 0;
    int cnt_cur;
    {   // first tile: list + prefill
        const int b = it >> 8, j = it & 255;
        cnt_cur = build_list(adj + (long)b * Nn * Nn + j,
                             idxb[0], cntb[0], tid, w, l);
        const float* ebj = efeat + (long)b * (Nn * Nn * Dd) + (long)j * Dd;
        const float* m2g = g_msg2 + ((long)b << 15);
        const int nc = (cnt_cur + 31) >> 5;
        if (nc > 0) stage_chunk(sb, ebj, m2g, idxb[0], 0, w, l);
        cp_commit();
        if (nc > 1) stage_chunk(sb, ebj, m2g, idxb[0], 1, w, l);
        cp_commit();
    }

    while (it < NTOT) {
        const int b = it >> 8, j = it & 255;
        const float* ebj = efeat + (long)b * (Nn * Nn * Dd) + (long)j * Dd;
        const float* m2g = g_msg2 + ((long)b << 15);
        const int* idxc = idxb[buf];
        const int cnt = cnt_cur;
        const int nc = (cnt + 31) >> 5;

        float cst[4], best[4];
        #pragma unroll
        for (int s = 0; s < 4; s++) {
            const int m = w * 32 + (s >> 1) * 16 + g + (s & 1) * 8;
            cst[s] = g_msg1[it * MIDn + m] + g_msgg[b * MIDn + m] + be[m];
            best[s] = -FLT_MAX;
        }

        #pragma unroll 1
        for (int c = 0; c < nc; c++) {
            cp_wait<1>();
            __syncthreads();
            const char* eb = smem + ((c & 1) ? SM_E1 : SM_E0);
            const float* m2s = (const float*)(smem + ((c & 1) ? SM_M1 : SM_M0));

            float acc[2][4][4];
            #pragma unroll
            for (int mt = 0; mt < 2; mt++)
                #pragma unroll
                for (int nt = 0; nt < 4; nt++)
                    #pragma unroll
                    for (int r = 0; r < 4; r++) acc[mt][nt][r] = 0.f;

            #pragma unroll
            for (int kt = 0; kt < 16; kt++) {
                #pragma unroll
                for (int nt = 0; nt < 4; nt++) {
                    const float2 bv = *(const float2*)(eb
                                       + (nt * 8 + g) * EPADB + kt * 32 + t * 8);
                    const unsigned b0 = __float_as_uint(bv.x);
                    const unsigned b1 = __float_as_uint(bv.y);
                    mma8(acc[0][nt], A[0][kt], b0, b1);
                    mma8(acc[1][nt], A[1][kt], b0, b1);
                }
            }

            #pragma unroll
            for (int nt = 0; nt < 4; nt++) {
                const int il = nt * 8 + 2 * t;
                const int slot = c * 32 + il;
                const float aj0 = (slot < cnt) ? 1.f : 0.f;
                const float aj1 = (slot + 1 < cnt) ? 1.f : 0.f;
                const int mwg = w * 32 + g;
                #pragma unroll
                for (int mt = 0; mt < 2; mt++)
                    #pragma unroll
                    for (int hh = 0; hh < 2; hh++) {
                        const int m = mwg + mt * 16 + hh * 8;
                        const int s = mt * 2 + hh;
                        const float v0 = (acc[mt][nt][2 * hh] + cst[s]
                                          + m2s[il * 132 + m]) * aj0;
                        const float v1 = (acc[mt][nt][2 * hh + 1] + cst[s]
                                          + m2s[(il + 1) * 132 + m]) * aj1;
                        best[s] = fmaxf(best[s], fmaxf(v0, v1));
                    }
            }
            __syncthreads();
            if (c + 2 < nc) stage_chunk(sb, ebj, m2g, idxc, c + 2, w, l);
            cp_commit();
        }

        // --- splice: build + prefill NEXT tile before epilogue ---
        const int itn = it + GRID;
        if (itn < NTOT) {
            const int bn = itn >> 8, jn = itn & 255;
            cnt_cur = build_list(adj + (long)bn * Nn * Nn + jn,
                                 idxb[buf ^ 1], cntb[buf ^ 1], tid, w, l);
            const float* ebjn = efeat + (long)bn * (Nn * Nn * Dd)
                                + (long)jn * Dd;
            const float* m2gn = g_msg2 + ((long)bn << 15);
            const int ncn = (cnt_cur + 31) >> 5;
            if (ncn > 0) stage_chunk(sb, ebjn, m2gn, idxb[buf ^ 1], 0, w, l);
            cp_commit();
            if (ncn > 1) stage_chunk(sb, ebjn, m2gn, idxb[buf ^ 1], 1, w, l);
            cp_commit();
        }

        // --- epilogue for current tile (overlaps next fill) ---
        if (cnt < Nn) {
            #pragma unroll
            for (int s = 0; s < 4; s++) best[s] = fmaxf(best[s], 0.f);
        }
        #pragma unroll
        for (int s = 0; s < 4; s++) {
            best[s] = fmaxf(best[s], __shfl_xor_sync(0xFFFFFFFFu, best[s], 1));
            best[s] = fmaxf(best[s], __shfl_xor_sync(0xFFFFFFFFu, best[s], 2));
        }
        __syncthreads();               // bestsm free (prev reads done)
        if (t == 0) {
            #pragma unroll
            for (int s = 0; s < 4; s++)
                bestsm[w * 32 + (s >> 1) * 16 + g + (s & 1) * 8] = best[s];
        }
        __syncthreads();

        float o = g_base[it * MIDn + tid];
        #pragma unroll 8
        for (int k = 0; k < MIDn; k++)
            o = fmaf(bestsm[k], __ldg(&Wo2[(k << 7) + tid]), o);
        out[it * MIDn + tid] = o;

        buf ^= 1;
        it = itn;
    }
}

// ========================================================================
extern "C" void kernel_launch(void* const* d_in, const int* in_sizes, int n_in,
                              void* d_out, int out_size)
{
    const float* hidden = (const float*)d_in[0];
    const float* nfeat  = (const float*)d_in[1];
    const float* efeat  = (const float*)d_in[2];
    const float* gfeat  = (const float*)d_in[3];
    const float* adj    = (const float*)d_in[4];
    const float* W1  = (const float*)d_in[5];
    const float* b1  = (const float*)d_in[6];
    const float* W2  = (const float*)d_in[7];
    const float* b2  = (const float*)d_in[8];
    const float* We  = (const float*)d_in[9];
    const float* be  = (const float*)d_in[10];
    const float* Wg  = (const float*)d_in[11];
    const float* bg  = (const float*)d_in[12];
    const float* Wo1 = (const float*)d_in[13];
    const float* bo1 = (const float*)d_in[14];
    const float* Wo2 = (const float*)d_in[15];
    const float* bo2 = (const float*)d_in[16];
    float* out = (float*)d_out;

    static int smem_set = 0;
    if (!smem_set) {
        cudaFuncSetAttribute(main_kernel,
                             cudaFuncAttributeMaxDynamicSharedMemorySize,
                             SM_TOTAL);
        smem_set = 1;
    }

    aux_kernel<<<296, 512>>>(hidden, nfeat, gfeat, W1, b1, W2, b2, We,
                             Wg, bg, Wo1, bo1, bo2);
    main_kernel<<<GRID, 128, SM_TOTAL>>>(efeat, adj, be, Wo2, out);
}